// round 8
// baseline (speedup 1.0000x reference)
#include <cuda_runtime.h>
#include <cuda_bf16.h>
#include <math.h>
#include <stdint.h>

#define NB   8
#define NH   8
#define DH   64
#define CC   512
#define NN   4096
#define HID  512
#define O3   1536
#define QSCALE 0.125f   // 64^-0.5
#define KTOT 512
#define BK   16                 // bf16 K per stage
#define KSTEPS (KTOT / BK)      // 32
#define ROWB 48                 // smem row stride bytes (16 bf16 = 32B + 16B pad)
#define TILEB (128 * ROWB)      // 6144 B per operand tile
#define STAGEB (4 * TILEB)      // 24576 B per stage (Ah,Al,Bh,Bl)
#define NSTAGE 4
#define NCHUNK 8                // ctx split-K chunks over n

// ---------------- scratch (static device arrays; sanctioned) ----------------
__device__ float g_qkv[(size_t)NB * O3 * NN];          // 201 MB fp32 q|k|v
__device__ float g_ctx[NB * NH * DH * DH];
__device__ float g_ctxp[NCHUNK][NB * NH][DH * DH];     // ctx partials (8 MB)
__device__ int   g_maskwide;
__device__ __nv_bfloat16 g_whi[O3 * CC],  g_wlo[O3 * CC];                            // w_qkv hi/lo
__device__ __nv_bfloat16 g_xhi[(size_t)NB * NN * CC], g_xlo[(size_t)NB * NN * CC];   // x^T
__device__ __nv_bfloat16 g_qhi[(size_t)NB * NN * HID], g_qlo[(size_t)NB * NN * HID]; // q_soft^T
__device__ __nv_bfloat16 g_wfhi[NB * CC * HID], g_wflo[NB * CC * HID];               // Weff

// ---------------- helpers ----------------
__device__ __forceinline__ uint32_t smem_u32(const void* p) {
    uint32_t a;
    asm("{ .reg .u64 t; cvta.to.shared.u64 t, %1; cvt.u32.u64 %0, t; }" : "=r"(a) : "l"(p));
    return a;
}
#define CP_ASYNC16(saddr, gptr) \
    asm volatile("cp.async.cg.shared.global [%0], [%1], 16;" :: "r"(saddr), "l"(gptr))
#define CP_COMMIT()  asm volatile("cp.async.commit_group;" ::: "memory")
#define CP_WAIT2()   asm volatile("cp.async.wait_group 2;" ::: "memory")
#define CP_WAIT1()   asm volatile("cp.async.wait_group 1;" ::: "memory")
#define CP_WAIT0()   asm volatile("cp.async.wait_group 0;" ::: "memory")

__device__ __forceinline__ void ldsm4(uint32_t* r, uint32_t addr) {
    asm volatile("ldmatrix.sync.aligned.m8n8.x4.shared.b16 {%0,%1,%2,%3}, [%4];"
                 : "=r"(r[0]), "=r"(r[1]), "=r"(r[2]), "=r"(r[3]) : "r"(addr));
}
__device__ __forceinline__ void mma_bf16(float* d, const uint32_t* a, uint32_t b0, uint32_t b1) {
    asm volatile("mma.sync.aligned.m16n8k16.row.col.f32.bf16.bf16.f32 "
                 "{%0,%1,%2,%3}, {%4,%5,%6,%7}, {%8,%9}, {%0,%1,%2,%3};"
                 : "+f"(d[0]), "+f"(d[1]), "+f"(d[2]), "+f"(d[3])
                 : "r"(a[0]), "r"(a[1]), "r"(a[2]), "r"(a[3]), "r"(b0), "r"(b1));
}

// ---------------------------------------------------------------------------
__global__ void sniff_mask_kernel(const unsigned char* __restrict__ mask8) {
    g_maskwide = (mask8[1] == 0) ? 1 : 0;
}

__device__ __forceinline__ void split_bf16(float v, __nv_bfloat16& hi, __nv_bfloat16& lo) {
    hi = __float2bfloat16(v);
    lo = __float2bfloat16(v - __bfloat162float(hi));
}

__global__ __launch_bounds__(256) void convert_w_kernel(const float* __restrict__ w) {
    int i = blockIdx.x * 256 + threadIdx.x;
    if (i < O3 * CC) { __nv_bfloat16 h, l; split_bf16(w[i], h, l); g_whi[i] = h; g_wlo[i] = l; }
}

// x [b][c][n] fp32 -> xT hi/lo [b][n][c] bf16
__global__ __launch_bounds__(256) void transpose_convert_x(const float* __restrict__ x) {
    __shared__ float t[32][33];
    const int b = blockIdx.z, n0 = blockIdx.x * 32, c0 = blockIdx.y * 32;
    const int tx = threadIdx.x, ty = threadIdx.y;              // 32 x 8
    const float* xp = x + ((long)b * CC + c0) * NN + n0;
    #pragma unroll
    for (int j = 0; j < 32; j += 8) t[ty + j][tx] = xp[(long)(ty + j) * NN + tx];
    __syncthreads();
    const long ob = ((long)b * NN + n0) * CC + c0;
    #pragma unroll
    for (int j = 0; j < 32; j += 8) {
        float v = t[tx][ty + j];
        __nv_bfloat16 h, l; split_bf16(v, h, l);
        g_xhi[ob + (long)(ty + j) * CC + tx] = h;
        g_xlo[ob + (long)(ty + j) * CC + tx] = l;
    }
}

// ---------------------------------------------------------------------------
// bf16x3 GEMM via mma.sync: C[128,128] = (Ahi+Alo)(Bhi+Blo)^T, fp32 accum.
// A [M,512] K-major hi/lo, B [N,512] K-major hi/lo. 256 thr, 8 warps 2x4,
// warp tile 64x32. BK=16, 4-stage cp.async, 2 CTAs/SM (96KB smem each).
// MMA issue order: term-major (16 independent accs between same-acc reuses).
// ---------------------------------------------------------------------------
template<bool BIAS>
__global__ __launch_bounds__(256, 2)
void mma_gemm_kernel(const __nv_bfloat16* __restrict__ Ahi, const __nv_bfloat16* __restrict__ Alo,
                     const __nv_bfloat16* __restrict__ Bhi, const __nv_bfloat16* __restrict__ Blo,
                     float* __restrict__ C, const float* __restrict__ bias,
                     long sA, long sB, long sC, int ldC)
{
    extern __shared__ char dsmem[];
    const int tid = threadIdx.x, lane = tid & 31, wid = tid >> 5;
    const int wm = wid >> 2, wn = wid & 3;            // warp 2x4
    const int m0 = blockIdx.y * 128, n0 = blockIdx.x * 128, bz = blockIdx.z;

    const __nv_bfloat16* Ah = Ahi + (long)bz * sA;
    const __nv_bfloat16* Al = Alo + (long)bz * sA;
    const __nv_bfloat16* Bh = Bhi + (long)bz * sB;
    const __nv_bfloat16* Bl = Blo + (long)bz * sB;

    const uint32_t sb = smem_u32(dsmem);

    // per-thread cp.async coords: each thread does one 16B chunk per tile
    const int cr = tid >> 1, cq = tid & 1;   // 128 rows x 2 chunks of 16B

    auto load_stage = [&](int st, int k0) {
        const uint32_t s = sb + st * STAGEB;
        const uint32_t soff = (uint32_t)(cr * ROWB + cq * 16);
        const long goff = (long)cr * KTOT + k0 + cq * 8;
        CP_ASYNC16(s + 0 * TILEB + soff, Ah + (long)m0 * KTOT + goff);
        CP_ASYNC16(s + 1 * TILEB + soff, Al + (long)m0 * KTOT + goff);
        CP_ASYNC16(s + 2 * TILEB + soff, Bh + (long)n0 * KTOT + goff);
        CP_ASYNC16(s + 3 * TILEB + soff, Bl + (long)n0 * KTOT + goff);
        CP_COMMIT();
    };

    // ldmatrix address bases (row = lane&15, col16 = lane>>4)
    const uint32_t aoff = (uint32_t)((wm * 64 + (lane & 15)) * ROWB + (lane >> 4) * 16);
    const uint32_t boff = (uint32_t)((wn * 32 + (lane & 15)) * ROWB + (lane >> 4) * 16);

    float acc[4][4][4];
    #pragma unroll
    for (int i = 0; i < 4; i++)
        #pragma unroll
        for (int j = 0; j < 4; j++)
            #pragma unroll
            for (int r = 0; r < 4; r++) acc[i][j][r] = 0.f;

    load_stage(0, 0);
    load_stage(1, BK);
    load_stage(2, 2 * BK);

    for (int s = 0; s < KSTEPS; s++) {
        if (s < KSTEPS - 2)      CP_WAIT2();
        else if (s == KSTEPS - 2) CP_WAIT1();
        else                      CP_WAIT0();
        __syncthreads();

        // prefetch 3 ahead into the stage freed by step s-1 (sync above guarantees)
        if (s + 3 < KSTEPS) load_stage((s + 3) % NSTAGE, (s + 3) * BK);

        const uint32_t stg = sb + (s % NSTAGE) * STAGEB;
        uint32_t ah[4][4], al[4][4], bhf[2][4], blf[2][4];
        #pragma unroll
        for (int mf = 0; mf < 4; mf++) {
            ldsm4(ah[mf], stg + 0 * TILEB + aoff + mf * (16 * ROWB));
            ldsm4(al[mf], stg + 1 * TILEB + aoff + mf * (16 * ROWB));
        }
        #pragma unroll
        for (int nf = 0; nf < 2; nf++) {
            ldsm4(bhf[nf], stg + 2 * TILEB + boff + nf * (16 * ROWB));
            ldsm4(blf[nf], stg + 3 * TILEB + boff + nf * (16 * ROWB));
        }
        // term-major order: every accumulator touched once per 16 issues,
        // so the 3 same-acc MMAs are ~16 issues apart (RAW latency hidden).
        #pragma unroll
        for (int t = 0; t < 3; t++) {
            #pragma unroll
            for (int mf = 0; mf < 4; mf++) {
                #pragma unroll
                for (int j = 0; j < 4; j++) {
                    const int nf = j >> 1, sel = j & 1;
                    if (t == 0)
                        mma_bf16(acc[mf][j], ah[mf], bhf[nf][sel], bhf[nf][sel + 2]);
                    else if (t == 1)
                        mma_bf16(acc[mf][j], ah[mf], blf[nf][sel], blf[nf][sel + 2]);
                    else
                        mma_bf16(acc[mf][j], al[mf], bhf[nf][sel], bhf[nf][sel + 2]);
                }
            }
        }
    }

    // epilogue: fragments -> smem [128][132] fp32 -> coalesced stores
    __syncthreads();
    float* eps = (float*)dsmem;
    const int fr = lane >> 2, fc = (lane & 3) * 2;
    #pragma unroll
    for (int mf = 0; mf < 4; mf++) {
        #pragma unroll
        for (int j = 0; j < 4; j++) {
            const int row = wm * 64 + mf * 16 + fr;
            const int col = wn * 32 + j * 8 + fc;
            eps[row * 132 + col]           = acc[mf][j][0];
            eps[row * 132 + col + 1]       = acc[mf][j][1];
            eps[(row + 8) * 132 + col]     = acc[mf][j][2];
            eps[(row + 8) * 132 + col + 1] = acc[mf][j][3];
        }
    }
    __syncthreads();

    float* Cp = C + (long)bz * sC + (long)m0 * ldC + n0;
    for (int i = tid; i < 128 * 32; i += 256) {
        const int r = i >> 5, c4 = (i & 31) << 2;
        float4 v = *(float4*)&eps[r * 132 + c4];
        if (BIAS) {
            const float bv = bias[m0 + r];
            v.x += bv; v.y += bv; v.z += bv; v.w += bv;
        }
        *(float4*)&Cp[(long)r * ldC + c4] = v;
    }
}

// ---------------------------------------------------------------------------
// q softmax over d, * scale; writes TRANSPOSED bf16 hi/lo [b][n][h*64+d]
__global__ __launch_bounds__(256)
void softmax_q_kernel()
{
    const int idx = blockIdx.x * 256 + threadIdx.x;
    const int n  = idx & (NN - 1);
    const int bh = idx >> 12;
    const int h  = bh & (NH - 1);
    const int b  = bh >> 3;
    const float* p = g_qkv + ((long)b * O3 + h * DH) * NN + n;

    float v[DH];
    float m = -INFINITY;
    #pragma unroll
    for (int d = 0; d < DH; d++) { v[d] = p[(long)d * NN]; m = fmaxf(m, v[d]); }
    float s = 0.f;
    #pragma unroll
    for (int d = 0; d < DH; d++) { v[d] = __expf(v[d] - m); s += v[d]; }
    const float inv = QSCALE / s;
    const long ob = ((long)b * NN + n) * HID + h * DH;
    #pragma unroll
    for (int d = 0; d < DH; d++) {
        __nv_bfloat16 hi, lo; split_bf16(v[d] * inv, hi, lo);
        g_qhi[ob + d] = hi; g_qlo[ob + d] = lo;
    }
}

// k: mask + softmax over n (4096). In-place fp32.
__global__ __launch_bounds__(256)
void softmax_k_kernel(const unsigned char* __restrict__ mask8)
{
    const int row = blockIdx.x;
    const int b = row >> 9;
    float* p = g_qkv + ((long)b * O3 + HID + (row & 511)) * NN;

    __shared__ float sv[NN];
    __shared__ float red[256];
    const int tid = threadIdx.x;
    const bool wide = (g_maskwide != 0);
    const int* mask32 = (const int*)mask8;

    float m = -INFINITY;
    for (int i = tid; i < NN; i += 256) {
        const bool on = wide ? (mask32[b * NN + i] != 0) : (mask8[b * NN + i] != 0);
        const float x = on ? p[i] : -INFINITY;
        sv[i] = x;
        m = fmaxf(m, x);
    }
    red[tid] = m; __syncthreads();
    for (int s = 128; s > 0; s >>= 1) { if (tid < s) red[tid] = fmaxf(red[tid], red[tid + s]); __syncthreads(); }
    m = red[0]; __syncthreads();

    float sum = 0.f;
    for (int i = tid; i < NN; i += 256) { const float e = __expf(sv[i] - m); sv[i] = e; sum += e; }
    red[tid] = sum; __syncthreads();
    for (int s = 128; s > 0; s >>= 1) { if (tid < s) red[tid] += red[tid + s]; __syncthreads(); }
    const float inv = 1.f / red[0];
    for (int i = tid; i < NN; i += 256) p[i] = sv[i] * inv;
}

// ---------------------------------------------------------------------------
// ctx partial: chunk c covers n in [c*512, (c+1)*512).
__global__ __launch_bounds__(256)
void ctx_part_kernel()
{
    const int bh = blockIdx.x;           // < 64
    const int ck = blockIdx.y;           // < NCHUNK
    const int b = bh >> 3, h = bh & 7;
    const float* Kp = g_qkv + ((long)b * O3 + HID     + h * DH) * NN;
    const float* Vp = g_qkv + ((long)b * O3 + 2 * HID + h * DH) * NN;
    const int nbeg = ck * (NN / NCHUNK), nend = nbeg + (NN / NCHUNK);

    __shared__ float Ks[32][64];
    __shared__ float Vs[32][64];
    const int tid = threadIdx.x;
    const int lr = tid >> 2, lc = (tid & 3) << 3;
    const int tx = tid & 15, ty = tid >> 4;

    float acc[4][4];
    #pragma unroll
    for (int i = 0; i < 4; i++)
        #pragma unroll
        for (int j = 0; j < 4; j++) acc[i][j] = 0.f;

    for (int n0 = nbeg; n0 < nend; n0 += 32) {
        float4 ka = *(const float4*)(Kp + (long)lr * NN + n0 + lc);
        float4 kb = *(const float4*)(Kp + (long)lr * NN + n0 + lc + 4);
        float4 va = *(const float4*)(Vp + (long)lr * NN + n0 + lc);
        float4 vb = *(const float4*)(Vp + (long)lr * NN + n0 + lc + 4);
        Ks[lc + 0][lr] = ka.x; Ks[lc + 1][lr] = ka.y; Ks[lc + 2][lr] = ka.z; Ks[lc + 3][lr] = ka.w;
        Ks[lc + 4][lr] = kb.x; Ks[lc + 5][lr] = kb.y; Ks[lc + 6][lr] = kb.z; Ks[lc + 7][lr] = kb.w;
        Vs[lc + 0][lr] = va.x; Vs[lc + 1][lr] = va.y; Vs[lc + 2][lr] = va.z; Vs[lc + 3][lr] = va.w;
        Vs[lc + 4][lr] = vb.x; Vs[lc + 5][lr] = vb.y; Vs[lc + 6][lr] = vb.z; Vs[lc + 7][lr] = vb.w;
        __syncthreads();
        #pragma unroll
        for (int c = 0; c < 32; c++) {
            float kr[4], vr[4];
            #pragma unroll
            for (int i = 0; i < 4; i++) kr[i] = Ks[c][ty * 4 + i];
            #pragma unroll
            for (int j = 0; j < 4; j++) vr[j] = Vs[c][tx * 4 + j];
            #pragma unroll
            for (int i = 0; i < 4; i++)
                #pragma unroll
                for (int j = 0; j < 4; j++)
                    acc[i][j] = fmaf(kr[i], vr[j], acc[i][j]);
        }
        __syncthreads();
    }
    float* Cp = g_ctxp[ck][bh];
    #pragma unroll
    for (int i = 0; i < 4; i++)
        #pragma unroll
        for (int j = 0; j < 4; j++)
            Cp[(ty * 4 + i) * DH + tx * 4 + j] = acc[i][j];
}

// reduce partials: g_ctx = sum_c g_ctxp[c]  (deterministic, fixed order)
__global__ __launch_bounds__(256)
void ctx_reduce_kernel()
{
    const int idx = blockIdx.x * 256 + threadIdx.x;   // < 64*4096
    const int bh = idx >> 12, e = idx & 4095;
    float s = 0.f;
    #pragma unroll
    for (int c = 0; c < NCHUNK; c++) s += g_ctxp[c][bh][e];
    g_ctx[(long)bh * (DH * DH) + e] = s;
}

// Weff[b][o][h*64+d] = sum_e w_out[o][h*64+e] * ctx[b][h][d][e] -> bf16 hi/lo
__global__ __launch_bounds__(256)
void weff_kernel(const float* __restrict__ w_out)
{
    const long idx = (long)blockIdx.x * 256 + threadIdx.x;
    const int hd = (int)(idx & 511);
    const int o  = (int)((idx >> 9) & 511);
    const int b  = (int)(idx >> 18);
    const int h = hd >> 6, d = hd & 63;

    const float* wr = w_out + (long)o * HID + h * DH;
    const float* cr = g_ctx + (((long)(b * NH + h) * DH) + d) * DH;
    float s = 0.f;
    #pragma unroll
    for (int e = 0; e < DH; e++) s = fmaf(wr[e], cr[e], s);
    __nv_bfloat16 hi, lo; split_bf16(s, hi, lo);
    g_wfhi[idx] = hi; g_wflo[idx] = lo;
}

// ---------------------------------------------------------------------------
extern "C" void kernel_launch(void* const* d_in, const int* in_sizes, int n_in,
                              void* d_out, int out_size)
{
    const float* x      = (const float*)d_in[0];
    const unsigned char* mask = (const unsigned char*)d_in[1];
    const float* w_qkv  = (const float*)d_in[2];
    const float* w_out  = (const float*)d_in[3];
    const float* b_out  = (const float*)d_in[4];
    float* out = (float*)d_out;

    float *qkv_p;
    __nv_bfloat16 *whi_p, *wlo_p, *xhi_p, *xlo_p, *qhi_p, *qlo_p, *wfhi_p, *wflo_p;
    cudaGetSymbolAddress((void**)&qkv_p,  g_qkv);
    cudaGetSymbolAddress((void**)&whi_p,  g_whi);
    cudaGetSymbolAddress((void**)&wlo_p,  g_wlo);
    cudaGetSymbolAddress((void**)&xhi_p,  g_xhi);
    cudaGetSymbolAddress((void**)&xlo_p,  g_xlo);
    cudaGetSymbolAddress((void**)&qhi_p,  g_qhi);
    cudaGetSymbolAddress((void**)&qlo_p,  g_qlo);
    cudaGetSymbolAddress((void**)&wfhi_p, g_wfhi);
    cudaGetSymbolAddress((void**)&wflo_p, g_wflo);

    const int DSMEM = NSTAGE * STAGEB;   // 98304 B -> 2 CTAs/SM
    cudaFuncSetAttribute(mma_gemm_kernel<false>, cudaFuncAttributeMaxDynamicSharedMemorySize, DSMEM);
    cudaFuncSetAttribute(mma_gemm_kernel<true>,  cudaFuncAttributeMaxDynamicSharedMemorySize, DSMEM);

    // 0) prep
    sniff_mask_kernel<<<1, 1>>>(mask);
    convert_w_kernel<<<(O3 * CC + 255) / 256, 256>>>(w_qkv);
    {
        dim3 g(NN / 32, CC / 32, NB);
        transpose_convert_x<<<g, dim3(32, 8)>>>(x);
    }
    // 1) qkv = w_qkv @ x   (tensor cores via mma.sync, bf16x3)
    {
        dim3 g(NN / 128, O3 / 128, NB);
        mma_gemm_kernel<false><<<g, 256, DSMEM>>>(
            whi_p, wlo_p, xhi_p, xlo_p, qkv_p, nullptr,
            0L, (long)NN * CC, (long)O3 * NN, NN);
    }
    // 2) q softmax -> qT hi/lo bf16
    softmax_q_kernel<<<(NB * NH * NN) / 256, 256>>>();
    // 3) k mask + softmax (in place, fp32)
    softmax_k_kernel<<<NB * HID, 256>>>(mask);
    // 4) context: split-K partials + deterministic reduce
    {
        dim3 g(NB * NH, NCHUNK);
        ctx_part_kernel<<<g, 256>>>();
        ctx_reduce_kernel<<<(NB * NH * DH * DH) / 256, 256>>>();
    }
    // 5) Weff (folded w_out x ctx) -> bf16 hi/lo
    weff_kernel<<<(NB * CC * HID) / 256, 256>>>(w_out);
    // 6) out = Weff[b] @ qT[b]^T + b_out
    {
        dim3 g(NN / 128, CC / 128, NB);
        mma_gemm_kernel<true><<<g, 256, DSMEM>>>(
            wfhi_p, wflo_p, qhi_p, qlo_p, out, b_out,
            (long)CC * HID, (long)NN * HID, (long)CC * NN, NN);
    }
}

// round 9
// speedup vs baseline: 1.3498x; 1.3498x over previous
#include <cuda_runtime.h>
#include <cuda.h>
#include <cuda_bf16.h>
#include <math.h>
#include <stdint.h>
#include <string.h>

#define NB   8
#define NH   8
#define DH   64
#define CC   512
#define NN   4096
#define HID  512
#define O3   1536
#define QSCALE 0.125f   // 64^-0.5
#define KTOT 512
#define BK   64                  // bf16 K per stage (128B rows, SW128)
#define KSTEPS (KTOT / BK)       // 8
#define TILEB (128 * 128)        // 16384 B per operand tile
#define STAGEB (4 * TILEB)       // 65536 B per stage (Ah,Al,Bh,Bl)
#define NSTAGE 3
#define NCHUNK 8                 // ctx split-K chunks over n

// ---------------- scratch (static device arrays; sanctioned) ----------------
__device__ float g_qkv[(size_t)NB * O3 * NN];          // 201 MB fp32 q|k|v
__device__ float g_ctx[NB * NH * DH * DH];
__device__ float g_ctxp[NCHUNK][NB * NH][DH * DH];
__device__ int   g_maskwide;
__device__ __align__(256) __nv_bfloat16 g_whi[O3 * CC],  g_wlo[O3 * CC];
__device__ __align__(256) __nv_bfloat16 g_xhi[(size_t)NB * NN * CC], g_xlo[(size_t)NB * NN * CC];
__device__ __align__(256) __nv_bfloat16 g_qhi[(size_t)NB * NN * HID], g_qlo[(size_t)NB * NN * HID];
__device__ __align__(256) __nv_bfloat16 g_wfhi[NB * CC * HID], g_wflo[NB * CC * HID];

// ---------------- device helpers ----------------
__device__ __forceinline__ uint32_t smem_u32(const void* p) {
    uint32_t a;
    asm("{ .reg .u64 t; cvta.to.shared.u64 t, %1; cvt.u32.u64 %0, t; }" : "=r"(a) : "l"(p));
    return a;
}
__device__ __forceinline__ void ldsm4(uint32_t* r, uint32_t addr) {
    asm volatile("ldmatrix.sync.aligned.m8n8.x4.shared.b16 {%0,%1,%2,%3}, [%4];"
                 : "=r"(r[0]), "=r"(r[1]), "=r"(r[2]), "=r"(r[3]) : "r"(addr));
}
__device__ __forceinline__ void mma_bf16(float* d, const uint32_t* a, uint32_t b0, uint32_t b1) {
    asm volatile("mma.sync.aligned.m16n8k16.row.col.f32.bf16.bf16.f32 "
                 "{%0,%1,%2,%3}, {%4,%5,%6,%7}, {%8,%9}, {%0,%1,%2,%3};"
                 : "+f"(d[0]), "+f"(d[1]), "+f"(d[2]), "+f"(d[3])
                 : "r"(a[0]), "r"(a[1]), "r"(a[2]), "r"(a[3]), "r"(b0), "r"(b1));
}
__device__ __forceinline__ void mbar_init(uint32_t a, uint32_t c) {
    asm volatile("mbarrier.init.shared.b64 [%0], %1;" :: "r"(a), "r"(c) : "memory");
}
__device__ __forceinline__ void mbar_expect(uint32_t a, uint32_t bytes) {
    asm volatile("mbarrier.arrive.expect_tx.shared.b64 _, [%0], %1;" :: "r"(a), "r"(bytes) : "memory");
}
__device__ __forceinline__ void mbar_wait(uint32_t mbar, uint32_t parity) {
    uint32_t done;
    asm volatile("{ .reg .pred p; mbarrier.try_wait.parity.acquire.cta.shared::cta.b64 p, [%1], %2; selp.b32 %0,1,0,p; }"
                 : "=r"(done) : "r"(mbar), "r"(parity) : "memory");
    if (!done) {
        asm volatile("{ .reg .pred P1; WL%=: mbarrier.try_wait.parity.acquire.cta.shared::cta.b64 P1, [%0], %1, 0x989680; @P1 bra.uni WD%=; bra.uni WL%=; WD%=: }"
                     :: "r"(mbar), "r"(parity) : "memory");
    }
}
__device__ __forceinline__ void tma3d(uint32_t dst, const CUtensorMap* m,
                                      int cx, int cy, int cz, uint32_t bar) {
    asm volatile("cp.async.bulk.tensor.3d.shared::cta.global.tile.mbarrier::complete_tx::bytes "
                 "[%0], [%1, {%2, %3, %4}], [%5];"
                 :: "r"(dst), "l"(m), "r"(cx), "r"(cy), "r"(cz), "r"(bar) : "memory");
}
__device__ __forceinline__ void split_bf16(float v, __nv_bfloat16& hi, __nv_bfloat16& lo) {
    hi = __float2bfloat16(v);
    lo = __float2bfloat16(v - __bfloat162float(hi));
}
__device__ __forceinline__ unsigned short bfbits(__nv_bfloat16 x) {
    unsigned short u; memcpy(&u, &x, 2); return u;
}

// ---------------------------------------------------------------------------
__global__ void sniff_mask_kernel(const unsigned char* __restrict__ mask8) {
    g_maskwide = (mask8[1] == 0) ? 1 : 0;
}

__global__ __launch_bounds__(256) void convert_w_kernel(const float* __restrict__ w) {
    int i = blockIdx.x * 256 + threadIdx.x;
    if (i < O3 * CC) { __nv_bfloat16 h, l; split_bf16(w[i], h, l); g_whi[i] = h; g_wlo[i] = l; }
}

// x [b][c][n] fp32 -> xT hi/lo [b][n][c] bf16. Tile 64c x 32n, coalesced both ways.
__global__ __launch_bounds__(256) void transpose_convert_x(const float* __restrict__ x) {
    __shared__ float t[64][33];
    const int b = blockIdx.z, n0 = blockIdx.x * 32, c0 = blockIdx.y * 64;
    const int tx = threadIdx.x, ty = threadIdx.y;              // 32 x 8
    #pragma unroll
    for (int cl = ty; cl < 64; cl += 8)
        t[cl][tx] = x[((long)b * CC + c0 + cl) * NN + n0 + tx];
    __syncthreads();
    // warp ty writes rows r = ty*4..ty*4+3; lane handles c-pair (2*lane, 2*lane+1)
    const int lane = tx;
    #pragma unroll
    for (int rr = 0; rr < 4; rr++) {
        const int r = ty * 4 + rr;
        float v0 = t[2 * lane][r], v1 = t[2 * lane + 1][r];
        __nv_bfloat16 h0, l0, h1, l1;
        split_bf16(v0, h0, l0); split_bf16(v1, h1, l1);
        const long base = ((long)b * NN + n0 + r) * CC + c0 + 2 * lane;
        *(uint32_t*)&g_xhi[base] = (uint32_t)bfbits(h0) | ((uint32_t)bfbits(h1) << 16);
        *(uint32_t*)&g_xlo[base] = (uint32_t)bfbits(l0) | ((uint32_t)bfbits(l1) << 16);
    }
}

// ---------------------------------------------------------------------------
// bf16x3 GEMM: TMA loads (SW128) + mma.sync. C[128,128] tile, fp32 accum.
// A [M,512] K-major hi/lo, B [N,512] K-major hi/lo. 256 thr, warps 2x4,
// warp tile 64x32. BK=64, 3-stage TMA pipeline.
// ---------------------------------------------------------------------------
template<bool BIAS>
__global__ __launch_bounds__(256)
void tma_gemm_kernel(const __grid_constant__ CUtensorMap tAh,
                     const __grid_constant__ CUtensorMap tAl,
                     const __grid_constant__ CUtensorMap tBh,
                     const __grid_constant__ CUtensorMap tBl,
                     float* __restrict__ C, const float* __restrict__ bias,
                     long sC, int ldC, int aBatch)
{
    extern __shared__ char dsmem[];
    __shared__ __align__(8) unsigned long long s_bar[NSTAGE];

    const int tid = threadIdx.x, lane = tid & 31, wid = tid >> 5;
    const int wm = wid >> 2, wn = wid & 3;            // warps 2x4
    const int m0 = blockIdx.y * 128, n0 = blockIdx.x * 128, bz = blockIdx.z;
    const int za = aBatch ? bz : 0;

    const uint32_t sb = (smem_u32(dsmem) + 1023u) & ~1023u;
    const uint32_t bar0 = smem_u32(&s_bar[0]);

    if (tid == 0) {
        #pragma unroll
        for (int i = 0; i < NSTAGE; i++) mbar_init(bar0 + i * 8, 1);
    }
    asm volatile("fence.proxy.async.shared::cta;" ::: "memory");
    __syncthreads();

    auto issue = [&](int s) {
        const int sl = s % NSTAGE;
        const uint32_t bar = bar0 + sl * 8;
        const uint32_t dst = sb + sl * STAGEB;
        const int k0 = s * BK;
        mbar_expect(bar, STAGEB);
        tma3d(dst + 0 * TILEB, &tAh, k0, m0, za, bar);
        tma3d(dst + 1 * TILEB, &tAl, k0, m0, za, bar);
        tma3d(dst + 2 * TILEB, &tBh, k0, n0, bz, bar);
        tma3d(dst + 3 * TILEB, &tBl, k0, n0, bz, bar);
    };
    if (tid == 0) { issue(0); issue(1); issue(2); }

    // ldmatrix swizzled addressing (SW128, 128B rows)
    const int lr = lane & 15;
    const uint32_t xorv = (uint32_t)((lane & 7) << 4);
    const uint32_t acol = (uint32_t)((lane >> 4) * 16);
    const uint32_t aRow = (uint32_t)((wm * 64 + lr) * 128);
    const uint32_t bRow = (uint32_t)((wn * 32 + lr) * 128);

    float acc[4][4][4];
    #pragma unroll
    for (int i = 0; i < 4; i++)
        #pragma unroll
        for (int j = 0; j < 4; j++)
            #pragma unroll
            for (int r = 0; r < 4; r++) acc[i][j][r] = 0.f;

    for (int s = 0; s < KSTEPS; s++) {
        mbar_wait(bar0 + (s % NSTAGE) * 8, (uint32_t)((s / NSTAGE) & 1));
        const uint32_t stg = sb + (s % NSTAGE) * STAGEB;

        #pragma unroll
        for (int k16 = 0; k16 < 4; k16++) {
            const uint32_t kb = (uint32_t)(k16 * 32);
            const uint32_t csw = (acol + kb) ^ xorv;
            uint32_t ah[4][4], al[4][4], bhf[2][4], blf[2][4];
            #pragma unroll
            for (int mf = 0; mf < 4; mf++) {
                const uint32_t ro = aRow + (uint32_t)(mf * 16 * 128) + csw;
                ldsm4(ah[mf], stg + 0 * TILEB + ro);
                ldsm4(al[mf], stg + 1 * TILEB + ro);
            }
            #pragma unroll
            for (int nf = 0; nf < 2; nf++) {
                const uint32_t ro = bRow + (uint32_t)(nf * 16 * 128) + csw;
                ldsm4(bhf[nf], stg + 2 * TILEB + ro);
                ldsm4(blf[nf], stg + 3 * TILEB + ro);
            }
            #pragma unroll
            for (int t = 0; t < 3; t++) {
                #pragma unroll
                for (int mf = 0; mf < 4; mf++) {
                    #pragma unroll
                    for (int j = 0; j < 4; j++) {
                        const int nf = j >> 1, sel = j & 1;
                        if (t == 0)
                            mma_bf16(acc[mf][j], ah[mf], bhf[nf][sel], bhf[nf][sel + 2]);
                        else if (t == 1)
                            mma_bf16(acc[mf][j], ah[mf], blf[nf][sel], blf[nf][sel + 2]);
                        else
                            mma_bf16(acc[mf][j], al[mf], bhf[nf][sel], bhf[nf][sel + 2]);
                    }
                }
            }
        }

        __syncthreads();
        if (s + NSTAGE < KSTEPS && tid == 0) issue(s + NSTAGE);
    }

    // epilogue: fragments -> smem [128][132] fp32 -> coalesced stores
    __syncthreads();
    float* eps = (float*)dsmem;
    const int fr = lane >> 2, fc = (lane & 3) * 2;
    #pragma unroll
    for (int mf = 0; mf < 4; mf++) {
        #pragma unroll
        for (int j = 0; j < 4; j++) {
            const int row = wm * 64 + mf * 16 + fr;
            const int col = wn * 32 + j * 8 + fc;
            eps[row * 132 + col]           = acc[mf][j][0];
            eps[row * 132 + col + 1]       = acc[mf][j][1];
            eps[(row + 8) * 132 + col]     = acc[mf][j][2];
            eps[(row + 8) * 132 + col + 1] = acc[mf][j][3];
        }
    }
    __syncthreads();

    float* Cp = C + (long)bz * sC + (long)m0 * ldC + n0;
    for (int i = tid; i < 128 * 32; i += 256) {
        const int r = i >> 5, c4 = (i & 31) << 2;
        float4 v = *(float4*)&eps[r * 132 + c4];
        if (BIAS) {
            const float bv = bias[m0 + r];
            v.x += bv; v.y += bv; v.z += bv; v.w += bv;
        }
        *(float4*)&Cp[(long)r * ldC + c4] = v;
    }
}

// ---------------------------------------------------------------------------
// q softmax over d, * scale; writes TRANSPOSED bf16 hi/lo [b][n][hid],
// staged through smem for coalesced global stores.
#define QPAD 520   // ushort row stride (1040 B, 8B-multiple)
__global__ __launch_bounds__(256)
void softmax_q_kernel()
{
    __shared__ unsigned short sq[32 * QPAD];
    const int b = blockIdx.y, n0 = blockIdx.x * 32;
    const int h = threadIdx.x >> 5, nl = threadIdx.x & 31;
    const int wid = h, lane = nl;
    const float* p = g_qkv + ((long)b * O3 + h * DH) * NN + n0 + nl;

    float v[DH];
    float m = -INFINITY;
    #pragma unroll
    for (int d = 0; d < DH; d++) { v[d] = p[(long)d * NN]; m = fmaxf(m, v[d]); }
    float s = 0.f;
    #pragma unroll
    for (int d = 0; d < DH; d++) { v[d] = __expf(v[d] - m); s += v[d]; }
    const float inv = QSCALE / s;
    #pragma unroll
    for (int d = 0; d < DH; d++) v[d] *= inv;

    // pass 1: hi
    #pragma unroll
    for (int d = 0; d < DH; d += 2) {
        __nv_bfloat16 h0, l0, h1, l1;
        split_bf16(v[d], h0, l0); split_bf16(v[d + 1], h1, l1);
        *(uint32_t*)&sq[nl * QPAD + h * 64 + d] =
            (uint32_t)bfbits(h0) | ((uint32_t)bfbits(h1) << 16);
    }
    __syncthreads();
    #pragma unroll
    for (int rr = 0; rr < 4; rr++) {
        const int r = wid * 4 + rr;
        const uint2* src = (const uint2*)&sq[r * QPAD];
        uint2* dst = (uint2*)(g_qhi + ((long)b * NN + n0 + r) * HID);
        #pragma unroll
        for (int c = 0; c < 4; c++) dst[c * 32 + lane] = src[c * 32 + lane];
    }
    __syncthreads();
    // pass 2: lo
    #pragma unroll
    for (int d = 0; d < DH; d += 2) {
        __nv_bfloat16 h0, l0, h1, l1;
        split_bf16(v[d], h0, l0); split_bf16(v[d + 1], h1, l1);
        *(uint32_t*)&sq[nl * QPAD + h * 64 + d] =
            (uint32_t)bfbits(l0) | ((uint32_t)bfbits(l1) << 16);
    }
    __syncthreads();
    #pragma unroll
    for (int rr = 0; rr < 4; rr++) {
        const int r = wid * 4 + rr;
        const uint2* src = (const uint2*)&sq[r * QPAD];
        uint2* dst = (uint2*)(g_qlo + ((long)b * NN + n0 + r) * HID);
        #pragma unroll
        for (int c = 0; c < 4; c++) dst[c * 32 + lane] = src[c * 32 + lane];
    }
}

// k: mask + softmax over n (4096). In-place fp32.
__global__ __launch_bounds__(256)
void softmax_k_kernel(const unsigned char* __restrict__ mask8)
{
    const int row = blockIdx.x;
    const int b = row >> 9;
    float* p = g_qkv + ((long)b * O3 + HID + (row & 511)) * NN;

    __shared__ float sv[NN];
    __shared__ float red[256];
    const int tid = threadIdx.x;
    const bool wide = (g_maskwide != 0);
    const int* mask32 = (const int*)mask8;

    float m = -INFINITY;
    for (int i = tid; i < NN; i += 256) {
        const bool on = wide ? (mask32[b * NN + i] != 0) : (mask8[b * NN + i] != 0);
        const float x = on ? p[i] : -INFINITY;
        sv[i] = x;
        m = fmaxf(m, x);
    }
    red[tid] = m; __syncthreads();
    for (int s = 128; s > 0; s >>= 1) { if (tid < s) red[tid] = fmaxf(red[tid], red[tid + s]); __syncthreads(); }
    m = red[0]; __syncthreads();

    float sum = 0.f;
    for (int i = tid; i < NN; i += 256) { const float e = __expf(sv[i] - m); sv[i] = e; sum += e; }
    red[tid] = sum; __syncthreads();
    for (int s = 128; s > 0; s >>= 1) { if (tid < s) red[tid] += red[tid + s]; __syncthreads(); }
    const float inv = 1.f / red[0];
    for (int i = tid; i < NN; i += 256) p[i] = sv[i] * inv;
}

// ---------------------------------------------------------------------------
__global__ __launch_bounds__(256)
void ctx_part_kernel()
{
    const int bh = blockIdx.x, ck = blockIdx.y;
    const int b = bh >> 3, h = bh & 7;
    const float* Kp = g_qkv + ((long)b * O3 + HID     + h * DH) * NN;
    const float* Vp = g_qkv + ((long)b * O3 + 2 * HID + h * DH) * NN;
    const int nbeg = ck * (NN / NCHUNK), nend = nbeg + (NN / NCHUNK);

    __shared__ float Ks[32][64];
    __shared__ float Vs[32][64];
    const int tid = threadIdx.x;
    const int lr = tid >> 2, lc = (tid & 3) << 3;
    const int tx = tid & 15, ty = tid >> 4;

    float acc[4][4];
    #pragma unroll
    for (int i = 0; i < 4; i++)
        #pragma unroll
        for (int j = 0; j < 4; j++) acc[i][j] = 0.f;

    for (int n0 = nbeg; n0 < nend; n0 += 32) {
        float4 ka = *(const float4*)(Kp + (long)lr * NN + n0 + lc);
        float4 kb = *(const float4*)(Kp + (long)lr * NN + n0 + lc + 4);
        float4 va = *(const float4*)(Vp + (long)lr * NN + n0 + lc);
        float4 vb = *(const float4*)(Vp + (long)lr * NN + n0 + lc + 4);
        Ks[lc + 0][lr] = ka.x; Ks[lc + 1][lr] = ka.y; Ks[lc + 2][lr] = ka.z; Ks[lc + 3][lr] = ka.w;
        Ks[lc + 4][lr] = kb.x; Ks[lc + 5][lr] = kb.y; Ks[lc + 6][lr] = kb.z; Ks[lc + 7][lr] = kb.w;
        Vs[lc + 0][lr] = va.x; Vs[lc + 1][lr] = va.y; Vs[lc + 2][lr] = va.z; Vs[lc + 3][lr] = va.w;
        Vs[lc + 4][lr] = vb.x; Vs[lc + 5][lr] = vb.y; Vs[lc + 6][lr] = vb.z; Vs[lc + 7][lr] = vb.w;
        __syncthreads();
        #pragma unroll
        for (int c = 0; c < 32; c++) {
            float kr[4], vr[4];
            #pragma unroll
            for (int i = 0; i < 4; i++) kr[i] = Ks[c][ty * 4 + i];
            #pragma unroll
            for (int j = 0; j < 4; j++) vr[j] = Vs[c][tx * 4 + j];
            #pragma unroll
            for (int i = 0; i < 4; i++)
                #pragma unroll
                for (int j = 0; j < 4; j++)
                    acc[i][j] = fmaf(kr[i], vr[j], acc[i][j]);
        }
        __syncthreads();
    }
    float* Cp = g_ctxp[ck][bh];
    #pragma unroll
    for (int i = 0; i < 4; i++)
        #pragma unroll
        for (int j = 0; j < 4; j++)
            Cp[(ty * 4 + i) * DH + tx * 4 + j] = acc[i][j];
}

__global__ __launch_bounds__(256)
void ctx_reduce_kernel()
{
    const int idx = blockIdx.x * 256 + threadIdx.x;
    const int bh = idx >> 12, e = idx & 4095;
    float s = 0.f;
    #pragma unroll
    for (int c = 0; c < NCHUNK; c++) s += g_ctxp[c][bh][e];
    g_ctx[(long)bh * (DH * DH) + e] = s;
}

__global__ __launch_bounds__(256)
void weff_kernel(const float* __restrict__ w_out)
{
    const long idx = (long)blockIdx.x * 256 + threadIdx.x;
    const int hd = (int)(idx & 511);
    const int o  = (int)((idx >> 9) & 511);
    const int b  = (int)(idx >> 18);
    const int h = hd >> 6, d = hd & 63;

    const float* wr = w_out + (long)o * HID + h * DH;
    const float* cr = g_ctx + (((long)(b * NH + h) * DH) + d) * DH;
    float s = 0.f;
    #pragma unroll
    for (int e = 0; e < DH; e++) s = fmaf(wr[e], cr[e], s);
    __nv_bfloat16 hi, lo; split_bf16(s, hi, lo);
    g_wfhi[idx] = hi; g_wflo[idx] = lo;
}

// ---------------------------------------------------------------------------
typedef CUresult (*EncFn)(CUtensorMap*, CUtensorMapDataType, cuuint32_t, void*,
                          const cuuint64_t*, const cuuint64_t*, const cuuint32_t*,
                          const cuuint32_t*, CUtensorMapInterleave, CUtensorMapSwizzle,
                          CUtensorMapL2promotion, CUtensorMapFloatOOBfill);

static void make_desc(EncFn enc, CUtensorMap* m, void* base,
                      uint64_t d0, uint64_t d1, uint64_t d2)
{
    cuuint64_t dims[3] = { d0, d1, d2 };
    cuuint64_t strides[2] = { d0 * 2, d0 * d1 * 2 };
    cuuint32_t box[3] = { 64, 128, 1 };
    cuuint32_t es[3] = { 1, 1, 1 };
    enc(m, CU_TENSOR_MAP_DATA_TYPE_BFLOAT16, 3, base, dims, strides, box, es,
        CU_TENSOR_MAP_INTERLEAVE_NONE, CU_TENSOR_MAP_SWIZZLE_128B,
        CU_TENSOR_MAP_L2_PROMOTION_L2_128B, CU_TENSOR_MAP_FLOAT_OOB_FILL_NONE);
}

extern "C" void kernel_launch(void* const* d_in, const int* in_sizes, int n_in,
                              void* d_out, int out_size)
{
    const float* x      = (const float*)d_in[0];
    const unsigned char* mask = (const unsigned char*)d_in[1];
    const float* w_qkv  = (const float*)d_in[2];
    const float* w_out  = (const float*)d_in[3];
    const float* b_out  = (const float*)d_in[4];
    float* out = (float*)d_out;

    float *qkv_p;
    __nv_bfloat16 *whi_p, *wlo_p, *xhi_p, *xlo_p, *qhi_p, *qlo_p, *wfhi_p, *wflo_p;
    cudaGetSymbolAddress((void**)&qkv_p,  g_qkv);
    cudaGetSymbolAddress((void**)&whi_p,  g_whi);
    cudaGetSymbolAddress((void**)&wlo_p,  g_wlo);
    cudaGetSymbolAddress((void**)&xhi_p,  g_xhi);
    cudaGetSymbolAddress((void**)&xlo_p,  g_xlo);
    cudaGetSymbolAddress((void**)&qhi_p,  g_qhi);
    cudaGetSymbolAddress((void**)&qlo_p,  g_qlo);
    cudaGetSymbolAddress((void**)&wfhi_p, g_wfhi);
    cudaGetSymbolAddress((void**)&wflo_p, g_wflo);

    // driver entry point (no -lcuda link needed)
    void* encf = nullptr;
    cudaDriverEntryPointQueryResult qr;
    cudaGetDriverEntryPoint("cuTensorMapEncodeTiled", &encf, cudaEnableDefault, &qr);
    EncFn enc = (EncFn)encf;

    CUtensorMap tWh, tWl, tXh, tXl, tQh, tQl, tFh, tFl;
    make_desc(enc, &tWh, whi_p,  512, 1536, 1);
    make_desc(enc, &tWl, wlo_p,  512, 1536, 1);
    make_desc(enc, &tXh, xhi_p,  512, 4096, 8);
    make_desc(enc, &tXl, xlo_p,  512, 4096, 8);
    make_desc(enc, &tQh, qhi_p,  512, 4096, 8);
    make_desc(enc, &tQl, qlo_p,  512, 4096, 8);
    make_desc(enc, &tFh, wfhi_p, 512, 512,  8);
    make_desc(enc, &tFl, wflo_p, 512, 512,  8);

    const int DSMEM = NSTAGE * STAGEB + 1024;   // 197632 B
    cudaFuncSetAttribute(tma_gemm_kernel<false>, cudaFuncAttributeMaxDynamicSharedMemorySize, DSMEM);
    cudaFuncSetAttribute(tma_gemm_kernel<true>,  cudaFuncAttributeMaxDynamicSharedMemorySize, DSMEM);

    // 0) prep
    sniff_mask_kernel<<<1, 1>>>(mask);
    convert_w_kernel<<<(O3 * CC + 255) / 256, 256>>>(w_qkv);
    {
        dim3 g(NN / 32, CC / 64, NB);
        transpose_convert_x<<<g, dim3(32, 8)>>>(x);
    }
    // 1) qkv = w_qkv @ x   (TMA + mma.sync bf16x3)
    {
        dim3 g(NN / 128, O3 / 128, NB);
        tma_gemm_kernel<false><<<g, 256, DSMEM>>>(
            tWh, tWl, tXh, tXl, qkv_p, nullptr, (long)O3 * NN, NN, 0);
    }
    // 2) q softmax -> qT hi/lo bf16 (coalesced)
    {
        dim3 g(NN / 32, NB);
        softmax_q_kernel<<<g, 256>>>();
    }
    // 3) k mask + softmax (in place, fp32)
    softmax_k_kernel<<<NB * HID, 256>>>(mask);
    // 4) context: split-K partials + deterministic reduce
    {
        dim3 g(NB * NH, NCHUNK);
        ctx_part_kernel<<<g, 256>>>();
        ctx_reduce_kernel<<<(NB * NH * DH * DH) / 256, 256>>>();
    }
    // 5) Weff (folded w_out x ctx) -> bf16 hi/lo
    weff_kernel<<<(NB * CC * HID) / 256, 256>>>(w_out);
    // 6) out = Weff[b] @ qT[b]^T + b_out
    {
        dim3 g(NN / 128, CC / 128, NB);
        tma_gemm_kernel<true><<<g, 256, DSMEM>>>(
            tFh, tFl, tQh, tQl, out, b_out, (long)CC * NN, NN, 1);
    }
}